// round 1
// baseline (speedup 1.0000x reference)
#include <cuda_runtime.h>

// SINDy library: out[row] = [1, z(32), z_i*z_j (i<=j, 528), z_a*z_b*z_c (a<=b<=c, 5984), sin(z)(32)]
// B = 8192 rows, N_DIM = 32, total columns = 6577. Output fp32.
// Pure HBM-write-bound: 215.5 MB stored per launch.

#define NDIM        32
#define NPAIRS      528
#define NTRIPLES    5984
#define NCOLS       6577      // 1 + 32 + 528 + 5984 + 32
#define PAIR_BASE   33
#define TRIPLE_BASE 561
#define SIN_BASE    6545
#define NROWS       8192

// Packed index tables (filled by init kernel each launch; deterministic & idempotent).
__device__ unsigned short g_pair[NPAIRS];     // i | (j<<8)
__device__ unsigned int   g_triple[NTRIPLES]; // a | (b<<8) | (c<<16)

__global__ void sindy_init_tables() {
    int a = threadIdx.x;
    if (a >= NDIM) return;

    // Pairs with first index a start at: sum_{k<a}(NDIM-k) = a*NDIM - a*(a-1)/2
    int poff = a * NDIM - (a * (a - 1)) / 2;
    for (int j = a; j < NDIM; ++j) {
        g_pair[poff + (j - a)] = (unsigned short)(a | (j << 8));
    }

    // Triples with first index a start after sum_{a'<a} T(NDIM-a'), T(m)=m(m+1)/2
    int toff = 0;
    for (int ap = 0; ap < a; ++ap) {
        int m = NDIM - ap;
        toff += (m * (m + 1)) / 2;
    }
    for (int b = a; b < NDIM; ++b) {
        for (int c = b; c < NDIM; ++c) {
            g_triple[toff++] = (unsigned int)(a | (b << 8) | (c << 16));
        }
    }
}

__global__ __launch_bounds__(256) void sindy_library_kernel(
    const float* __restrict__ z, float* __restrict__ out)
{
    __shared__ float s_z[NDIM];
    __shared__ float s_sin[NDIM];

    const int row = blockIdx.x;
    const int t   = threadIdx.x;

    if (t < NDIM) {
        float v = z[row * NDIM + t];
        s_z[t]   = v;
        s_sin[t] = sinf(v);
    }
    __syncthreads();

    float* __restrict__ o = out + (size_t)row * NCOLS;

    #pragma unroll 4
    for (int c = t; c < NCOLS; c += 256) {
        float v;
        if (c == 0) {
            v = 1.0f;
        } else if (c < PAIR_BASE) {
            v = s_z[c - 1];
        } else if (c < TRIPLE_BASE) {
            unsigned int p = (unsigned int)__ldg(&g_pair[c - PAIR_BASE]);
            v = s_z[p & 0xFFu] * s_z[p >> 8];
        } else if (c < SIN_BASE) {
            unsigned int q = __ldg(&g_triple[c - TRIPLE_BASE]);
            v = s_z[q & 0xFFu] * s_z[(q >> 8) & 0xFFu] * s_z[(q >> 16) & 0xFFu];
        } else {
            v = s_sin[c - SIN_BASE];
        }
        o[c] = v;
    }
}

extern "C" void kernel_launch(void* const* d_in, const int* in_sizes, int n_in,
                              void* d_out, int out_size) {
    const float* z   = (const float*)d_in[0];
    float*       out = (float*)d_out;

    sindy_init_tables<<<1, 32>>>();
    sindy_library_kernel<<<NROWS, 256>>>(z, out);
}

// round 2
// speedup vs baseline: 1.4313x; 1.4313x over previous
#include <cuda_runtime.h>

// SINDy library: out[row] = [1, z(32), z_i*z_j (i<=j, 528), z_a*z_b*z_c (a<=b<=c, 5984), sin(z)(32)]
// B = 8192 rows, 6577 cols, fp32 out. 215.5 MB written -> target HBM write roofline.
//
// Key structure: value(col) = s_mul[a] * s_buf[k]
//   s_mul[0..31] = z, s_mul[32] = 1.0
//   s_buf[0] = 1, s_buf[1..32] = z, s_buf[33..560] = pair products, s_buf[561..592] = sin(z)
//   For triples (a,b,c): k = 33 + pairidx(b,c); consecutive triple cols -> consecutive k
//   (conflict-free shared reads), a changes rarely (broadcast).
// Per-column decode table is built at COMPILE TIME (constexpr) -> no init kernel.

#define NDIM   32
#define NPAIRS 528
#define NCOLS  6577
#define SBUF_N 593   // 1 + 32 + 528 + 32

struct ColTbl  { unsigned short e[NCOLS]; };
struct PairTbl { unsigned short e[NPAIRS]; };

static constexpr int pair_index(int i, int j) {
    // triu_indices order: p = i*32 - i*(i-1)/2 + (j - i)
    return i * NDIM - (i * (i - 1)) / 2 + (j - i);
}

static constexpr ColTbl make_col_tbl() {
    ColTbl t{};
    // col 0: 1 * 1
    t.e[0] = (unsigned short)(0u | (32u << 10));
    // cols 1..32: z  (1 * s_buf[col])
    for (int i = 0; i < NDIM; ++i)
        t.e[1 + i] = (unsigned short)((unsigned)(1 + i) | (32u << 10));
    // cols 33..560: pairs (1 * s_buf[col])
    for (int c = 33; c < 33 + NPAIRS; ++c)
        t.e[c] = (unsigned short)((unsigned)c | (32u << 10));
    // cols 561..6544: triples (a,b,c) -> s_mul[a] * s_buf[33 + pairidx(b,c)]
    {
        int col = 561;
        for (int a = 0; a < NDIM; ++a)
            for (int b = a; b < NDIM; ++b)
                for (int c = b; c < NDIM; ++c) {
                    unsigned k = 33u + (unsigned)pair_index(b, c);
                    t.e[col++] = (unsigned short)(k | ((unsigned)a << 10));
                }
    }
    // cols 6545..6576: sin(z)
    for (int i = 0; i < NDIM; ++i)
        t.e[6545 + i] = (unsigned short)((unsigned)(561 + i) | (32u << 10));
    return t;
}

static constexpr PairTbl make_pair_tbl() {
    PairTbl t{};
    int p = 0;
    for (int i = 0; i < NDIM; ++i)
        for (int j = i; j < NDIM; ++j)
            t.e[p++] = (unsigned short)((unsigned)i | ((unsigned)j << 8));
    return t;
}

__device__ constexpr ColTbl  G_COL  = make_col_tbl();
__device__ constexpr PairTbl G_PAIR = make_pair_tbl();

__global__ __launch_bounds__(256) void sindy_library_kernel(
    const float* __restrict__ z, float* __restrict__ out, int nrows)
{
    __shared__ float s_mul[NDIM + 1];  // z, 1.0
    __shared__ float s_buf[SBUF_N];    // 1, z, pairs, sin

    const int row = blockIdx.x;
    const int t   = threadIdx.x;

    if (t < NDIM) {
        float v = z[row * NDIM + t];
        s_mul[t]       = v;
        s_buf[1 + t]   = v;
        s_buf[561 + t] = sinf(v);
    } else if (t == NDIM) {
        s_mul[NDIM] = 1.0f;
        s_buf[0]    = 1.0f;
    }
    __syncthreads();

    // Build 528 pair products (528/256 -> ~2 per thread)
    #pragma unroll
    for (int p = t; p < NPAIRS; p += 256) {
        unsigned ij = (unsigned)G_PAIR.e[p];
        s_buf[33 + p] = s_mul[ij & 31u] * s_mul[(ij >> 8) & 31u];
    }
    __syncthreads();

    float* __restrict__ o = out + (size_t)row * NCOLS;

    #pragma unroll 4
    for (int c = t; c < NCOLS; c += 256) {
        unsigned e = (unsigned)__ldg(&G_COL.e[c]);
        o[c] = s_mul[e >> 10] * s_buf[e & 1023u];
    }
}

extern "C" void kernel_launch(void* const* d_in, const int* in_sizes, int n_in,
                              void* d_out, int out_size) {
    const float* z   = (const float*)d_in[0];
    float*       out = (float*)d_out;
    int nrows = out_size / NCOLS;   // 8192
    sindy_library_kernel<<<nrows, 256>>>(z, out, nrows);
}

// round 3
// speedup vs baseline: 1.4470x; 1.0109x over previous
#include <cuda_runtime.h>

// SINDy library: out[row] = [1, z(32), z_i*z_j (528), z_a*z_b*z_c (5984), sin(z)(32)]
// 8192 rows x 6577 cols fp32. value(col) = s_mul[a] * s_buf[k].
// Vectorized: float4 stores + LDS.128 reads from phase-shifted s_buf copies.

#define NDIM     32
#define NPAIRS   528
#define NCOLS    6577
#define SBUF_N   593           // 1 + 32 + 528 + 32
#define SBUF_PAD 596           // multiple of 4 for float4 rows
#define MAXG     1645

static constexpr int pair_index(int i, int j) {
    return i * NDIM - (i * (i - 1)) / 2 + (j - i);
}

struct ColTbl  { unsigned short e[NCOLS]; };   // per column: k | (a<<10)
struct GrpTbl  { unsigned int   e[4][MAXG]; }; // per phase/group: k0 | (a<<10), bit31 = boundary
struct PairTbl { unsigned short e[NPAIRS]; };  // i | (j<<8)

static constexpr ColTbl make_col_tbl() {
    ColTbl t{};
    // cols [0, 561): k = c, a = 32 (identity multiplier); covers 1, z, pairs
    for (int c = 0; c < 561; ++c)
        t.e[c] = (unsigned short)((unsigned)c | (32u << 10));
    // triples
    {
        int col = 561;
        for (int a = 0; a < NDIM; ++a)
            for (int b = a; b < NDIM; ++b)
                for (int c = b; c < NDIM; ++c) {
                    unsigned k = 33u + (unsigned)pair_index(b, c);
                    t.e[col++] = (unsigned short)(k | ((unsigned)a << 10));
                }
    }
    // sin: k = 561 + (c - 6545), a = 32
    for (int i = 0; i < NDIM; ++i)
        t.e[6545 + i] = (unsigned short)((unsigned)(561 + i) | (32u << 10));
    return t;
}

__device__ constexpr ColTbl G_COL = make_col_tbl();

static constexpr GrpTbl make_grp_tbl() {
    ColTbl ct = make_col_tbl();
    GrpTbl g{};
    for (int p = 0; p < 4; ++p) {
        int ng = (NCOLS - p) / 4;
        for (int gi = 0; gi < ng; ++gi) {
            int c0 = p + 4 * gi;
            unsigned k0 = ct.e[c0] & 1023u;
            unsigned a0 = (unsigned)(ct.e[c0] >> 10);
            bool uniform = true;
            for (int j = 1; j < 4; ++j) {
                unsigned kj = ct.e[c0 + j] & 1023u;
                unsigned aj = (unsigned)(ct.e[c0 + j] >> 10);
                if (kj != k0 + (unsigned)j || aj != a0) { uniform = false; break; }
            }
            g.e[p][gi] = uniform ? (k0 | (a0 << 10)) : 0x80000000u;
        }
    }
    return g;
}

__device__ constexpr GrpTbl G_GRP = make_grp_tbl();

static constexpr PairTbl make_pair_tbl() {
    PairTbl t{};
    int p = 0;
    for (int i = 0; i < NDIM; ++i)
        for (int j = i; j < NDIM; ++j)
            t.e[p++] = (unsigned short)((unsigned)i | ((unsigned)j << 8));
    return t;
}

__device__ constexpr PairTbl G_PAIR = make_pair_tbl();

__global__ __launch_bounds__(256) void sindy_library_kernel(
    const float* __restrict__ z, float* __restrict__ out)
{
    // 4 shifted copies: s_copy[P][P + k] = s_buf[k]; so reading k0..k0+3 from
    // copy P = (-k0)&3 gives a 16B-aligned LDS.128.
    __shared__ __align__(16) float s_copy[4][SBUF_PAD];
    __shared__ float s_mul[NDIM + 1];

    const int row = blockIdx.x;
    const int t   = threadIdx.x;

    if (t < NDIM) {
        float v = z[row * NDIM + t];
        float sv = __sinf(v);
        s_mul[t] = v;
        #pragma unroll
        for (int P = 0; P < 4; ++P) {
            s_copy[P][P + 1 + t]   = v;
            s_copy[P][P + 561 + t] = sv;
        }
    } else if (t == NDIM) {
        s_mul[NDIM] = 1.0f;
        #pragma unroll
        for (int P = 0; P < 4; ++P) s_copy[P][P + 0] = 1.0f;
    }
    __syncthreads();

    // Build 528 pair products into all 4 shifted copies.
    #pragma unroll
    for (int p = t; p < NPAIRS; p += 256) {
        unsigned ij = (unsigned)G_PAIR.e[p];
        float v = s_mul[ij & 31u] * s_mul[(ij >> 8) & 31u];
        #pragma unroll
        for (int P = 0; P < 4; ++P) s_copy[P][P + 33 + p] = v;
    }
    __syncthreads();

    float* __restrict__ o = out + (size_t)row * NCOLS;

    // Phase: need (row + c0) % 4 == 0 for 16B-aligned float4 stores.
    const int ph = (4 - (row & 3)) & 3;

    // Head (< 4 scalar columns)
    if (t < ph) {
        unsigned e = (unsigned)G_COL.e[t];
        o[t] = s_mul[e >> 10] * s_copy[0][e & 1023u];
    }

    const int ng = (NCOLS - ph) >> 2;
    for (int g = t; g < ng; g += 256) {
        const int c0 = ph + (g << 2);
        unsigned e = __ldg(&G_GRP.e[ph][g]);
        float vv[4];
        if ((int)e >= 0) {
            unsigned k0 = e & 1023u;
            float za = s_mul[(e >> 10) & 63u];
            unsigned P = (unsigned)(-(int)k0) & 3u;
            float4 b = *(const float4*)&s_copy[P][k0 + P];
            vv[0] = za * b.x; vv[1] = za * b.y; vv[2] = za * b.z; vv[3] = za * b.w;
        } else {
            #pragma unroll
            for (int j = 0; j < 4; ++j) {
                unsigned ee = (unsigned)G_COL.e[c0 + j];
                vv[j] = s_mul[ee >> 10] * s_copy[0][ee & 1023u];
            }
        }
        *(float4*)(o + c0) = make_float4(vv[0], vv[1], vv[2], vv[3]);
    }

    // Tail (< 4 scalar columns)
    {
        int c = ph + (ng << 2) + t;
        if (c < NCOLS) {
            unsigned e = (unsigned)G_COL.e[c];
            o[c] = s_mul[e >> 10] * s_copy[0][e & 1023u];
        }
    }
}

extern "C" void kernel_launch(void* const* d_in, const int* in_sizes, int n_in,
                              void* d_out, int out_size) {
    const float* z   = (const float*)d_in[0];
    float*       out = (float*)d_out;
    sindy_library_kernel<<<8192, 256>>>(z, out);
}